// round 5
// baseline (speedup 1.0000x reference)
#include <cuda_runtime.h>
#include <cuda_fp16.h>
#include <math.h>
#include <stdint.h>

#define D_EMBED 2048
#define NHEAD   8
#define HDIM    256
#define BATCH   32
#define SEQ     256
#define ROWS    (BATCH*SEQ)   /* 8192 */
#define DFF     (4*D_EMBED)   /* 8192 */
#define BH      (BATCH*NHEAD) /* 256 */

// ---------------- scratch (device globals; no runtime allocation) -------------
__device__ __half g_hhi [ROWS*D_EMBED];
__device__ __half g_hlo [ROWS*D_EMBED];
__device__ __half g_qhi [ROWS*D_EMBED];
__device__ __half g_qlo [ROWS*D_EMBED];
__device__ __half g_khi [ROWS*D_EMBED];
__device__ __half g_klo [ROWS*D_EMBED];
__device__ float  g_v   [ROWS*D_EMBED];
__device__ __half g_vthi[ROWS*D_EMBED];
__device__ __half g_vtlo[ROWS*D_EMBED];
__device__ float  g_s   [BH*SEQ*SEQ];
__device__ __half g_shi [BH*SEQ*SEQ];
__device__ __half g_slo [BH*SEQ*SEQ];
__device__ __half g_aohi[ROWS*D_EMBED];
__device__ __half g_aolo[ROWS*D_EMBED];
__device__ float  g_x1  [ROWS*D_EMBED];
__device__ __half g_h2hi[ROWS*D_EMBED];
__device__ __half g_h2lo[ROWS*D_EMBED];
__device__ __half g_m1hi[(size_t)ROWS*DFF];
__device__ __half g_m1lo[(size_t)ROWS*DFF];
__device__ __half g_wqthi[D_EMBED*D_EMBED];
__device__ __half g_wqtlo[D_EMBED*D_EMBED];
__device__ __half g_wkthi[D_EMBED*D_EMBED];
__device__ __half g_wktlo[D_EMBED*D_EMBED];
__device__ __half g_wvthi[D_EMBED*D_EMBED];
__device__ __half g_wvtlo[D_EMBED*D_EMBED];
__device__ __half g_wothi[D_EMBED*D_EMBED];
__device__ __half g_wotlo[D_EMBED*D_EMBED];
__device__ __half g_w1thi[(size_t)D_EMBED*DFF];
__device__ __half g_w1tlo[(size_t)D_EMBED*DFF];
__device__ __half g_w2thi[(size_t)D_EMBED*DFF];
__device__ __half g_w2tlo[(size_t)D_EMBED*DFF];

// ---------------- helpers ------------------------------------------------------
__device__ __forceinline__ uint32_t smem_u32(const void* p) {
    uint32_t a;
    asm("{ .reg .u64 t; cvta.to.shared.u64 t, %1; cvt.u32.u64 %0, t; }" : "=r"(a) : "l"(p));
    return a;
}
__device__ __forceinline__ void cp16(uint32_t sdst, const void* gsrc) {
    asm volatile("cp.async.cg.shared.global [%0], [%1], 16;" :: "r"(sdst), "l"(gsrc));
}
#define CP_COMMIT() asm volatile("cp.async.commit_group;" ::: "memory")
#define CP_WAIT0()  asm volatile("cp.async.wait_group 0;" ::: "memory")

__device__ __forceinline__ void split16(float x, __half& hi, __half& lo) {
    hi = __float2half_rn(x);
    lo = __float2half_rn(x - __half2float(hi));
}
__device__ __forceinline__ void mma16(float* c, uint32_t a0, uint32_t a1,
                                      uint32_t a2, uint32_t a3,
                                      uint32_t b0, uint32_t b1) {
    asm volatile(
        "mma.sync.aligned.m16n8k16.row.col.f32.f16.f16.f32 "
        "{%0,%1,%2,%3}, {%4,%5,%6,%7}, {%8,%9}, {%0,%1,%2,%3};"
        : "+f"(c[0]), "+f"(c[1]), "+f"(c[2]), "+f"(c[3])
        : "r"(a0), "r"(a1), "r"(a2), "r"(a3), "r"(b0), "r"(b1));
}

// ---------------- layernorm (fp32 in -> fp16 hi/lo out) -----------------------
__global__ void __launch_bounds__(256) ln_kernel(const float* __restrict__ x,
                                                 const float* __restrict__ g,
                                                 const float* __restrict__ b,
                                                 __half* __restrict__ ohi,
                                                 __half* __restrict__ olo)
{
    __shared__ float red[256];
    const int row = blockIdx.x;
    const float* xr = x + (size_t)row * D_EMBED;
    const int tid = threadIdx.x;

    float v[8]; float s = 0.f;
#pragma unroll
    for (int i = 0; i < 8; i++) { v[i] = xr[tid + 256*i]; s += v[i]; }
    red[tid] = s; __syncthreads();
#pragma unroll
    for (int o = 128; o > 0; o >>= 1) { if (tid < o) red[tid] += red[tid+o]; __syncthreads(); }
    const float mean = red[0] * (1.0f / D_EMBED);
    __syncthreads();
    float qv = 0.f;
#pragma unroll
    for (int i = 0; i < 8; i++) { float d = v[i] - mean; qv += d*d; }
    red[tid] = qv; __syncthreads();
#pragma unroll
    for (int o = 128; o > 0; o >>= 1) { if (tid < o) red[tid] += red[tid+o]; __syncthreads(); }
    const float rstd = rsqrtf(red[0] * (1.0f / D_EMBED) + 1e-5f);

#pragma unroll
    for (int i = 0; i < 8; i++) {
        const int c = tid + 256*i;
        float o = (v[i] - mean) * rstd * g[c] + b[c];
        __half hi, lo; split16(o, hi, lo);
        ohi[(size_t)row * D_EMBED + c] = hi;
        olo[(size_t)row * D_EMBED + c] = lo;
    }
}

// ---------------- causal softmax (fp32 in -> fp16 hi/lo out) -------------------
__global__ void __launch_bounds__(256) softmax_kernel(const float* __restrict__ s,
                                                      __half* __restrict__ ohi,
                                                      __half* __restrict__ olo)
{
    __shared__ float red[256];
    const int row = blockIdx.x;
    const int t = row & (SEQ - 1);
    const float* sr = s + (size_t)row * SEQ;
    const int tid = threadIdx.x;

    const float val = (tid <= t) ? sr[tid] : -INFINITY;
    red[tid] = val; __syncthreads();
#pragma unroll
    for (int o = 128; o > 0; o >>= 1) { if (tid < o) red[tid] = fmaxf(red[tid], red[tid+o]); __syncthreads(); }
    const float mx = red[0];
    __syncthreads();
    const float e = (tid <= t) ? expf(val - mx) : 0.f;
    red[tid] = e; __syncthreads();
#pragma unroll
    for (int o = 128; o > 0; o >>= 1) { if (tid < o) red[tid] += red[tid+o]; __syncthreads(); }
    const float p = e / red[0];
    __half hi, lo; split16(p, hi, lo);
    ohi[(size_t)row * SEQ + tid] = hi;
    olo[(size_t)row * SEQ + tid] = lo;
}

// ---------------- transpose + split: fp32 [R x C] -> fp16 hi/lo [C x R] --------
__global__ void __launch_bounds__(256) transpose_split(
    const float* __restrict__ src, __half* __restrict__ dhi, __half* __restrict__ dlo,
    int R, int lds, int innerCnt, long sO, long sI, long dStride)
{
    __shared__ float t[32][33];
    const int z = blockIdx.z;
    const int zo = z / innerCnt, zi = z - zo * innerCnt;
    const float* s = src + (size_t)zo * sO + (size_t)zi * sI;
    __half* hi = dhi + (size_t)z * dStride;
    __half* lo = dlo + (size_t)z * dStride;
    const int c0 = blockIdx.x * 32, r0 = blockIdx.y * 32;
    const int x = threadIdx.x & 31, y = threadIdx.x >> 5;  // 32 x 8
#pragma unroll
    for (int i = 0; i < 32; i += 8)
        t[y + i][x] = s[(size_t)(r0 + y + i) * lds + c0 + x];
    __syncthreads();
#pragma unroll
    for (int i = 0; i < 32; i += 8) {
        float v = t[x][y + i];
        __half h, l; split16(v, h, l);
        size_t o = (size_t)(c0 + y + i) * R + r0 + x;
        hi[o] = h; lo[o] = l;
    }
}

// ---------------- fp16x3 mma.sync GEMM: 128x256 CTA tile, BK=32 ----------------
// 8 warps: 2 (M) x 4 (N); warp tile 64x64.
#define EP_BIAS   1
#define EP_GELU   2
#define EP_RES    4
#define EP_SPLIT  8
#define EP_STOREC 16

#define BK      32
#define ROWH    40                       /* halves per smem row (32 + pad 8) */
#define ROWB    (ROWH*2)                 /* 80 bytes                          */
#define ATILE_B (128 * ROWB)             /* 10240                              */
#define BTILE_B (256 * ROWB)             /* 20480                              */
#define STAGE_B (2*ATILE_B + 2*BTILE_B)  /* 61440                              */
#define SMEM_B  (2 * STAGE_B)            /* 122880                             */
#define OFF_AHI 0
#define OFF_ALO (ATILE_B)
#define OFF_BHI (2*ATILE_B)
#define OFF_BLO (2*ATILE_B + BTILE_B)

__device__ __forceinline__ void load_tileA(const __half* __restrict__ G, int ld,
                                           int row0, int k0, uint32_t sbase, int tid)
{
#pragma unroll
    for (int it = 0; it < 2; it++) {
        const int c = tid + it * 256;     // 0..511
        const int r = c >> 2, cb = c & 3;
        cp16(sbase + r * ROWB + cb * 16,
             G + (size_t)(row0 + r) * ld + k0 + cb * 8);
    }
}
__device__ __forceinline__ void load_tileB(const __half* __restrict__ G, int ld,
                                           int row0, int k0, uint32_t sbase, int tid)
{
#pragma unroll
    for (int it = 0; it < 4; it++) {
        const int c = tid + it * 256;     // 0..1023
        const int r = c >> 2, cb = c & 3;
        cp16(sbase + r * ROWB + cb * 16,
             G + (size_t)(row0 + r) * ld + k0 + cb * 8);
    }
}

__global__ void __launch_bounds__(256, 1) gemm_hmma(
    const __half* __restrict__ Ahi, const __half* __restrict__ Alo,
    const __half* __restrict__ Bhi, const __half* __restrict__ Blo,
    const float* __restrict__ bias, const float* __restrict__ Rs,
    float* __restrict__ C, __half* __restrict__ Chi, __half* __restrict__ Clo,
    int K, int lda, int ldb, int ldc, int innerCnt,
    long aO, long aI, long bO, long bI, long cO, long cI,
    float alpha, int mode, int causal)
{
    extern __shared__ __align__(128) char sm[];

    const int bm = blockIdx.y * 128;
    const int bn = blockIdx.x * 256;
    if (causal && bn > bm + 127) return;

    const int tid = threadIdx.x, wid = tid >> 5, lane = tid & 31;
    const int wm = (wid >> 2) * 64;     // 0 or 64
    const int wn = (wid & 3) * 64;      // 0,64,128,192
    const int lr = lane >> 2;           // 0..7
    const int lc2 = (lane & 3) * 2;     // 0,2,4,6

    const int z = blockIdx.z, zo = z / innerCnt, zi = z - zo * innerCnt;
    const __half* Ah = Ahi + (size_t)zo * aO + (size_t)zi * aI;
    const __half* Al = Alo + (size_t)zo * aO + (size_t)zi * aI;
    const __half* Bh = Bhi + (size_t)zo * bO + (size_t)zi * bI;
    const __half* Bl = Blo + (size_t)zo * bO + (size_t)zi * bI;
    const long coff = (size_t)zo * cO + (size_t)zi * cI;

    const uint32_t sb = smem_u32(sm);
    const int NB = K / BK;

    // prologue: block 0 -> stage 0
    load_tileA(Ah, lda, bm, 0, sb + OFF_AHI, tid);
    load_tileA(Al, lda, bm, 0, sb + OFF_ALO, tid);
    load_tileB(Bh, ldb, bn, 0, sb + OFF_BHI, tid);
    load_tileB(Bl, ldb, bn, 0, sb + OFF_BLO, tid);
    CP_COMMIT();
    CP_WAIT0();
    __syncthreads();

    float acc[4][8][4];
#pragma unroll
    for (int i = 0; i < 4; i++)
#pragma unroll
        for (int j = 0; j < 8; j++)
#pragma unroll
            for (int t = 0; t < 4; t++) acc[i][j][t] = 0.f;

    for (int blk = 0; blk < NB; blk++) {
        const int buf = blk & 1;
        if (blk + 1 < NB) {
            const uint32_t nb = sb + (buf ^ 1) * STAGE_B;
            const int kk = (blk + 1) * BK;
            load_tileA(Ah, lda, bm, kk, nb + OFF_AHI, tid);
            load_tileA(Al, lda, bm, kk, nb + OFF_ALO, tid);
            load_tileB(Bh, ldb, bn, kk, nb + OFF_BHI, tid);
            load_tileB(Bl, ldb, bn, kk, nb + OFF_BLO, tid);
            CP_COMMIT();
        }

        const __half* ah = (const __half*)(sm + buf * STAGE_B + OFF_AHI);
        const __half* al = (const __half*)(sm + buf * STAGE_B + OFF_ALO);
        const __half* bh = (const __half*)(sm + buf * STAGE_B + OFF_BHI);
        const __half* bl = (const __half*)(sm + buf * STAGE_B + OFF_BLO);

#pragma unroll
        for (int ks = 0; ks < BK / 16; ks++) {
            const int koff = ks * 16;

            uint32_t aH[4][4], aL[4][4];
#pragma unroll
            for (int mt = 0; mt < 4; mt++) {
                const int base = (wm + mt * 16 + lr) * ROWH + koff + lc2;
                aH[mt][0] = *(const uint32_t*)&ah[base];
                aH[mt][1] = *(const uint32_t*)&ah[base + 8 * ROWH];
                aH[mt][2] = *(const uint32_t*)&ah[base + 8];
                aH[mt][3] = *(const uint32_t*)&ah[base + 8 * ROWH + 8];
                aL[mt][0] = *(const uint32_t*)&al[base];
                aL[mt][1] = *(const uint32_t*)&al[base + 8 * ROWH];
                aL[mt][2] = *(const uint32_t*)&al[base + 8];
                aL[mt][3] = *(const uint32_t*)&al[base + 8 * ROWH + 8];
            }
#pragma unroll
            for (int nt = 0; nt < 8; nt++) {
                const int base = (wn + nt * 8 + lr) * ROWH + koff + lc2;
                const uint32_t bH0 = *(const uint32_t*)&bh[base];
                const uint32_t bH1 = *(const uint32_t*)&bh[base + 8];
                const uint32_t bL0 = *(const uint32_t*)&bl[base];
                const uint32_t bL1 = *(const uint32_t*)&bl[base + 8];
#pragma unroll
                for (int mt = 0; mt < 4; mt++) {
                    mma16(acc[mt][nt], aH[mt][0], aH[mt][1], aH[mt][2], aH[mt][3], bH0, bH1);
                    mma16(acc[mt][nt], aL[mt][0], aL[mt][1], aL[mt][2], aL[mt][3], bH0, bH1);
                    mma16(acc[mt][nt], aH[mt][0], aH[mt][1], aH[mt][2], aH[mt][3], bL0, bL1);
                }
            }
        }

        if (blk + 1 < NB) CP_WAIT0();
        __syncthreads();
    }

    // ---- epilogue ----
#pragma unroll
    for (int mt = 0; mt < 4; mt++) {
#pragma unroll
        for (int half = 0; half < 2; half++) {
            const int rr = bm + wm + mt * 16 + lr + half * 8;
            float* crow = C + coff + (size_t)rr * ldc;
            const float* rrow = Rs + coff + (size_t)rr * ldc;
            __half* hrow = Chi + coff + (size_t)rr * ldc;
            __half* lrow = Clo + coff + (size_t)rr * ldc;
#pragma unroll
            for (int nt = 0; nt < 8; nt++) {
                const int col = bn + wn + nt * 8 + lc2;
                float o0 = alpha * acc[mt][nt][half * 2 + 0];
                float o1 = alpha * acc[mt][nt][half * 2 + 1];
                if (mode & EP_BIAS) {
                    const float2 bb = *(const float2*)(bias + col);
                    o0 += bb.x; o1 += bb.y;
                }
                if (mode & EP_GELU) {
                    o0 *= normcdff(o0);
                    o1 *= normcdff(o1);
                }
                if (mode & EP_RES) {
                    const float2 rv = *(const float2*)(rrow + col);
                    o0 += rv.x; o1 += rv.y;
                }
                if (mode & EP_STOREC)
                    *(float2*)(crow + col) = make_float2(o0, o1);
                if (mode & EP_SPLIT) {
                    __half h0, l0, h1, l1;
                    split16(o0, h0, l0);
                    split16(o1, h1, l1);
                    *(__half2*)(hrow + col) = __halves2half2(h0, h1);
                    *(__half2*)(lrow + col) = __halves2half2(l0, l1);
                }
            }
        }
    }
}

// ---------------- host-side launch helper -------------------------------------
static void gemm5(const __half* Ahi, const __half* Alo,
                  const __half* Bhi, const __half* Blo,
                  const float* bias, const float* res,
                  float* C, __half* Chi, __half* Clo,
                  int M, int N, int K, int lda, int ldb, int ldc, int mode,
                  float alpha = 1.f, int causal = 0, int batch = 1, int innerCnt = 1,
                  long aO = 0, long aI = 0, long bO = 0, long bI = 0,
                  long cO = 0, long cI = 0)
{
    static int attrDone = 0;
    if (!attrDone) {
        cudaFuncSetAttribute(gemm_hmma, cudaFuncAttributeMaxDynamicSharedMemorySize, SMEM_B);
        attrDone = 1;
    }
    dim3 grid(N / 256, M / 128, batch);
    gemm_hmma<<<grid, 256, SMEM_B>>>(Ahi, Alo, Bhi, Blo, bias, res, C, Chi, Clo,
                                     K, lda, ldb, ldc, innerCnt,
                                     aO, aI, bO, bI, cO, cI, alpha, mode, causal);
}

extern "C" void kernel_launch(void* const* d_in, const int* in_sizes, int n_in,
                              void* d_out, int out_size)
{
    const float* x    = (const float*)d_in[0];
    const float* ln1g = (const float*)d_in[1];
    const float* ln1b = (const float*)d_in[2];
    const float* wq   = (const float*)d_in[3];
    const float* bq   = (const float*)d_in[4];
    const float* wk   = (const float*)d_in[5];
    const float* bk   = (const float*)d_in[6];
    const float* wv   = (const float*)d_in[7];
    const float* bv   = (const float*)d_in[8];
    const float* wo   = (const float*)d_in[9];
    const float* bo   = (const float*)d_in[10];
    const float* ln2g = (const float*)d_in[11];
    const float* ln2b = (const float*)d_in[12];
    const float* w1   = (const float*)d_in[13];
    const float* b1   = (const float*)d_in[14];
    const float* w2   = (const float*)d_in[15];
    const float* b2   = (const float*)d_in[16];
    float* out = (float*)d_out;

    void* p;
#define GET(var, symn, T) cudaGetSymbolAddress(&p, symn); T* var = (T*)p
    GET(hhi, g_hhi, __half);  GET(hlo, g_hlo, __half);
    GET(qhi, g_qhi, __half);  GET(qlo, g_qlo, __half);
    GET(khi, g_khi, __half);  GET(klo, g_klo, __half);
    GET(v,   g_v,   float);
    GET(vthi,g_vthi,__half);  GET(vtlo,g_vtlo,__half);
    GET(s,   g_s,   float);
    GET(shi, g_shi, __half);  GET(slo, g_slo, __half);
    GET(aohi,g_aohi,__half);  GET(aolo,g_aolo,__half);
    GET(x1,  g_x1,  float);
    GET(h2hi,g_h2hi,__half);  GET(h2lo,g_h2lo,__half);
    GET(m1hi,g_m1hi,__half);  GET(m1lo,g_m1lo,__half);
    GET(wqthi,g_wqthi,__half); GET(wqtlo,g_wqtlo,__half);
    GET(wkthi,g_wkthi,__half); GET(wktlo,g_wktlo,__half);
    GET(wvthi,g_wvthi,__half); GET(wvtlo,g_wvtlo,__half);
    GET(wothi,g_wothi,__half); GET(wotlo,g_wotlo,__half);
    GET(w1thi,g_w1thi,__half); GET(w1tlo,g_w1tlo,__half);
    GET(w2thi,g_w2thi,__half); GET(w2tlo,g_w2tlo,__half);
#undef GET

    // weight transposes + splits: w[k][n] -> wt[n][k] fp16 hi/lo
    {
        dim3 blk(256);
        transpose_split<<<dim3(D_EMBED/32, D_EMBED/32, 1), blk>>>(wq, wqthi, wqtlo, D_EMBED, D_EMBED, 1, 0, 0, 0);
        transpose_split<<<dim3(D_EMBED/32, D_EMBED/32, 1), blk>>>(wk, wkthi, wktlo, D_EMBED, D_EMBED, 1, 0, 0, 0);
        transpose_split<<<dim3(D_EMBED/32, D_EMBED/32, 1), blk>>>(wv, wvthi, wvtlo, D_EMBED, D_EMBED, 1, 0, 0, 0);
        transpose_split<<<dim3(D_EMBED/32, D_EMBED/32, 1), blk>>>(wo, wothi, wotlo, D_EMBED, D_EMBED, 1, 0, 0, 0);
        transpose_split<<<dim3(DFF/32,     D_EMBED/32, 1), blk>>>(w1, w1thi, w1tlo, D_EMBED, DFF,     1, 0, 0, 0);
        transpose_split<<<dim3(D_EMBED/32, DFF/32,     1), blk>>>(w2, w2thi, w2tlo, DFF,     D_EMBED, 1, 0, 0, 0);
    }

    // 1. h = LN1(x) -> split
    ln_kernel<<<ROWS, 256>>>(x, ln1g, ln1b, hhi, hlo);

    // 2. Q, K (split out), V (fp32 out)
    gemm5(hhi, hlo, wqthi, wqtlo, bq, nullptr, nullptr, qhi, qlo,
          ROWS, D_EMBED, D_EMBED, D_EMBED, D_EMBED, D_EMBED, EP_BIAS | EP_SPLIT);
    gemm5(hhi, hlo, wkthi, wktlo, bk, nullptr, nullptr, khi, klo,
          ROWS, D_EMBED, D_EMBED, D_EMBED, D_EMBED, D_EMBED, EP_BIAS | EP_SPLIT);
    gemm5(hhi, hlo, wvthi, wvtlo, bv, nullptr, v, nullptr, nullptr,
          ROWS, D_EMBED, D_EMBED, D_EMBED, D_EMBED, D_EMBED, EP_BIAS | EP_STOREC);

    // 3. per-head transpose-split of V: vt[z][d][t]
    transpose_split<<<dim3(HDIM/32, SEQ/32, BH), 256>>>(
        v, vthi, vtlo, SEQ, D_EMBED, NHEAD,
        (long)SEQ * D_EMBED, (long)HDIM, (long)SEQ * HDIM);

    // 4. scores = (1/16) Q K^T  (batched over b,h; causal tile skip)
    gemm5(qhi, qlo, khi, klo, nullptr, nullptr, s, nullptr, nullptr,
          SEQ, SEQ, HDIM, D_EMBED, D_EMBED, SEQ, EP_STOREC,
          0.0625f, /*causal=*/1, BH, NHEAD,
          (long)SEQ * D_EMBED, (long)HDIM,
          (long)SEQ * D_EMBED, (long)HDIM,
          (long)NHEAD * SEQ * SEQ, (long)SEQ * SEQ);

    // 5. causal softmax -> split
    softmax_kernel<<<BH * SEQ, 256>>>(s, shi, slo);

    // 6. ao = att @ V  (split out)
    gemm5(shi, slo, vthi, vtlo, nullptr, nullptr, nullptr, aohi, aolo,
          SEQ, HDIM, SEQ, SEQ, SEQ, D_EMBED, EP_SPLIT,
          1.0f, 0, BH, NHEAD,
          (long)NHEAD * SEQ * SEQ, (long)SEQ * SEQ,
          (long)NHEAD * SEQ * HDIM, (long)SEQ * HDIM,
          (long)SEQ * D_EMBED, (long)HDIM);

    // 7. x1 = x + ao @ Wo + bo
    gemm5(aohi, aolo, wothi, wotlo, bo, x, x1, nullptr, nullptr,
          ROWS, D_EMBED, D_EMBED, D_EMBED, D_EMBED, D_EMBED,
          EP_BIAS | EP_RES | EP_STOREC);

    // 8. h2 = LN2(x1) -> split
    ln_kernel<<<ROWS, 256>>>(x1, ln2g, ln2b, h2hi, h2lo);

    // 9. m1 = gelu(h2 @ W1 + b1) -> split
    gemm5(h2hi, h2lo, w1thi, w1tlo, b1, nullptr, nullptr, m1hi, m1lo,
          ROWS, DFF, D_EMBED, D_EMBED, D_EMBED, DFF, EP_BIAS | EP_GELU | EP_SPLIT);

    // 10. out = x1 + m1 @ W2 + b2
    gemm5(m1hi, m1lo, w2thi, w2tlo, b2, x1, out, nullptr, nullptr,
          ROWS, D_EMBED, DFF, DFF, DFF, D_EMBED, EP_BIAS | EP_RES | EP_STOREC);
}

// round 6
// speedup vs baseline: 1.2229x; 1.2229x over previous
#include <cuda_runtime.h>
#include <cuda_fp16.h>
#include <math.h>
#include <stdint.h>

#define D_EMBED 2048
#define NHEAD   8
#define HDIM    256
#define BATCH   32
#define SEQ     256
#define ROWS    (BATCH*SEQ)   /* 8192 */
#define DFF     (4*D_EMBED)   /* 8192 */
#define BH      (BATCH*NHEAD) /* 256 */

// ---------------- scratch (device globals; no runtime allocation) -------------
__device__ __half g_hhi [ROWS*D_EMBED];
__device__ __half g_hlo [ROWS*D_EMBED];
__device__ __half g_qhi [ROWS*D_EMBED];
__device__ __half g_qlo [ROWS*D_EMBED];
__device__ __half g_khi [ROWS*D_EMBED];
__device__ __half g_klo [ROWS*D_EMBED];
__device__ float  g_v   [ROWS*D_EMBED];
__device__ __half g_vthi[ROWS*D_EMBED];
__device__ __half g_vtlo[ROWS*D_EMBED];
__device__ float  g_s   [BH*SEQ*SEQ];
__device__ __half g_shi [BH*SEQ*SEQ];
__device__ __half g_slo [BH*SEQ*SEQ];
__device__ __half g_aohi[ROWS*D_EMBED];
__device__ __half g_aolo[ROWS*D_EMBED];
__device__ float  g_x1  [ROWS*D_EMBED];
__device__ __half g_h2hi[ROWS*D_EMBED];
__device__ __half g_h2lo[ROWS*D_EMBED];
__device__ __half g_m1hi[(size_t)ROWS*DFF];
__device__ __half g_m1lo[(size_t)ROWS*DFF];
__device__ __half g_wqthi[D_EMBED*D_EMBED];
__device__ __half g_wqtlo[D_EMBED*D_EMBED];
__device__ __half g_wkthi[D_EMBED*D_EMBED];
__device__ __half g_wktlo[D_EMBED*D_EMBED];
__device__ __half g_wvthi[D_EMBED*D_EMBED];
__device__ __half g_wvtlo[D_EMBED*D_EMBED];
__device__ __half g_wothi[D_EMBED*D_EMBED];
__device__ __half g_wotlo[D_EMBED*D_EMBED];
__device__ __half g_w1thi[(size_t)D_EMBED*DFF];
__device__ __half g_w1tlo[(size_t)D_EMBED*DFF];
__device__ __half g_w2thi[(size_t)D_EMBED*DFF];
__device__ __half g_w2tlo[(size_t)D_EMBED*DFF];

// ---------------- helpers ------------------------------------------------------
__device__ __forceinline__ uint32_t smem_u32(const void* p) {
    uint32_t a;
    asm("{ .reg .u64 t; cvta.to.shared.u64 t, %1; cvt.u32.u64 %0, t; }" : "=r"(a) : "l"(p));
    return a;
}
__device__ __forceinline__ void cp16(uint32_t sdst, const void* gsrc) {
    asm volatile("cp.async.cg.shared.global [%0], [%1], 16;" :: "r"(sdst), "l"(gsrc));
}
#define CP_COMMIT() asm volatile("cp.async.commit_group;" ::: "memory")
#define CP_WAIT0()  asm volatile("cp.async.wait_group 0;" ::: "memory")

__device__ __forceinline__ void split16(float x, __half& hi, __half& lo) {
    hi = __float2half_rn(x);
    lo = __float2half_rn(x - __half2float(hi));
}
__device__ __forceinline__ void mma16(float* c, const uint32_t a[4],
                                      uint32_t b0, uint32_t b1) {
    asm volatile(
        "mma.sync.aligned.m16n8k16.row.col.f32.f16.f16.f32 "
        "{%0,%1,%2,%3}, {%4,%5,%6,%7}, {%8,%9}, {%0,%1,%2,%3};"
        : "+f"(c[0]), "+f"(c[1]), "+f"(c[2]), "+f"(c[3])
        : "r"(a[0]), "r"(a[1]), "r"(a[2]), "r"(a[3]), "r"(b0), "r"(b1));
}
__device__ __forceinline__ void ldsm4(uint32_t& r0, uint32_t& r1, uint32_t& r2,
                                      uint32_t& r3, uint32_t addr) {
    asm volatile("ldmatrix.sync.aligned.m8n8.x4.shared.b16 {%0,%1,%2,%3}, [%4];"
                 : "=r"(r0), "=r"(r1), "=r"(r2), "=r"(r3) : "r"(addr));
}

// ---------------- layernorm (fp32 in -> fp16 hi/lo out) -----------------------
__global__ void __launch_bounds__(256) ln_kernel(const float* __restrict__ x,
                                                 const float* __restrict__ g,
                                                 const float* __restrict__ b,
                                                 __half* __restrict__ ohi,
                                                 __half* __restrict__ olo)
{
    __shared__ float red[256];
    const int row = blockIdx.x;
    const float* xr = x + (size_t)row * D_EMBED;
    const int tid = threadIdx.x;

    float v[8]; float s = 0.f;
#pragma unroll
    for (int i = 0; i < 8; i++) { v[i] = xr[tid + 256*i]; s += v[i]; }
    red[tid] = s; __syncthreads();
#pragma unroll
    for (int o = 128; o > 0; o >>= 1) { if (tid < o) red[tid] += red[tid+o]; __syncthreads(); }
    const float mean = red[0] * (1.0f / D_EMBED);
    __syncthreads();
    float qv = 0.f;
#pragma unroll
    for (int i = 0; i < 8; i++) { float d = v[i] - mean; qv += d*d; }
    red[tid] = qv; __syncthreads();
#pragma unroll
    for (int o = 128; o > 0; o >>= 1) { if (tid < o) red[tid] += red[tid+o]; __syncthreads(); }
    const float rstd = rsqrtf(red[0] * (1.0f / D_EMBED) + 1e-5f);

#pragma unroll
    for (int i = 0; i < 8; i++) {
        const int c = tid + 256*i;
        float o = (v[i] - mean) * rstd * g[c] + b[c];
        __half hi, lo; split16(o, hi, lo);
        ohi[(size_t)row * D_EMBED + c] = hi;
        olo[(size_t)row * D_EMBED + c] = lo;
    }
}

// ---------------- causal softmax (fp32 in -> fp16 hi/lo out) -------------------
__global__ void __launch_bounds__(256) softmax_kernel(const float* __restrict__ s,
                                                      __half* __restrict__ ohi,
                                                      __half* __restrict__ olo)
{
    __shared__ float red[256];
    const int row = blockIdx.x;
    const int t = row & (SEQ - 1);
    const float* sr = s + (size_t)row * SEQ;
    const int tid = threadIdx.x;

    const float val = (tid <= t) ? sr[tid] : -INFINITY;
    red[tid] = val; __syncthreads();
#pragma unroll
    for (int o = 128; o > 0; o >>= 1) { if (tid < o) red[tid] = fmaxf(red[tid], red[tid+o]); __syncthreads(); }
    const float mx = red[0];
    __syncthreads();
    const float e = (tid <= t) ? expf(val - mx) : 0.f;
    red[tid] = e; __syncthreads();
#pragma unroll
    for (int o = 128; o > 0; o >>= 1) { if (tid < o) red[tid] += red[tid+o]; __syncthreads(); }
    const float p = e / red[0];
    __half hi, lo; split16(p, hi, lo);
    ohi[(size_t)row * SEQ + tid] = hi;
    olo[(size_t)row * SEQ + tid] = lo;
}

// ---------------- transpose + split: fp32 [R x C] -> fp16 hi/lo [C x R] --------
__global__ void __launch_bounds__(256) transpose_split(
    const float* __restrict__ src, __half* __restrict__ dhi, __half* __restrict__ dlo,
    int R, int lds, int innerCnt, long sO, long sI, long dStride)
{
    __shared__ float t[32][33];
    const int z = blockIdx.z;
    const int zo = z / innerCnt, zi = z - zo * innerCnt;
    const float* s = src + (size_t)zo * sO + (size_t)zi * sI;
    __half* hi = dhi + (size_t)z * dStride;
    __half* lo = dlo + (size_t)z * dStride;
    const int c0 = blockIdx.x * 32, r0 = blockIdx.y * 32;
    const int x = threadIdx.x & 31, y = threadIdx.x >> 5;  // 32 x 8
#pragma unroll
    for (int i = 0; i < 32; i += 8)
        t[y + i][x] = s[(size_t)(r0 + y + i) * lds + c0 + x];
    __syncthreads();
#pragma unroll
    for (int i = 0; i < 32; i += 8) {
        float v = t[x][y + i];
        __half h, l; split16(v, h, l);
        size_t o = (size_t)(c0 + y + i) * R + r0 + x;
        hi[o] = h; lo[o] = l;
    }
}

// ---------------- fp16x3 mma.sync GEMM: 128x128 tile, BK=64 --------------------
// 8 warps: 2 (M) x 4 (N); warp tile 64x32. ldmatrix fragment loads + 3-pass mma.
#define EP_BIAS   1
#define EP_GELU   2
#define EP_RES    4
#define EP_SPLIT  8
#define EP_STOREC 16

#define BK      64
#define ROWH    72                      /* halves per smem row (pad 64+8)  */
#define ROWB    (ROWH*2)                /* 144 bytes                        */
#define TILE_B  (128 * ROWB)            /* 18432 bytes per tile             */
#define BUF_B   (4 * TILE_B)            /* Ahi,Alo,Bhi,Blo = 73728          */
#define SMEM_B  (2 * BUF_B)             /* double buffered = 147456         */

__device__ __forceinline__ void load_tile_async(const __half* __restrict__ G, int ld,
                                                int row0, int k0, uint32_t sbase, int tid)
{
#pragma unroll
    for (int it = 0; it < 4; it++) {
        const int c = tid + it * 256;         // 0..1023
        const int r = c >> 3, cb = c & 7;
        cp16(sbase + r * ROWB + cb * 16,
             G + (size_t)(row0 + r) * ld + k0 + cb * 8);
    }
}

__global__ void __launch_bounds__(256, 1) gemm_hmma(
    const __half* __restrict__ Ahi, const __half* __restrict__ Alo,
    const __half* __restrict__ Bhi, const __half* __restrict__ Blo,
    const float* __restrict__ bias, const float* __restrict__ Rs,
    float* __restrict__ C, __half* __restrict__ Chi, __half* __restrict__ Clo,
    int K, int lda, int ldb, int ldc, int innerCnt,
    long aO, long aI, long bO, long bI, long cO, long cI,
    float alpha, int mode, int causal)
{
    extern __shared__ __align__(128) char sm[];

    const int bm = blockIdx.y * 128;
    const int bn = blockIdx.x * 128;
    if (causal && bn > bm) return;

    const int tid = threadIdx.x, wid = tid >> 5, lane = tid & 31;
    const int wm = (wid >> 2) * 64;     // 0 or 64
    const int wn = (wid & 3) * 32;      // 0,32,64,96
    const int lr = lane >> 2;           // 0..7
    const int lc2 = (lane & 3) * 2;     // 0,2,4,6

    // ldmatrix per-lane offsets (halves within a tile)
    const int q = lane >> 3, rw = lane & 7;
    const int aoff = ((q & 1) * 8 + rw) * ROWH + (q >> 1) * 8;  // A: x4 -> a0,a1,a2,a3
    const int boff = ((q >> 1) * 8 + rw) * ROWH + (q & 1) * 8;  // B: x4 -> nt-pair b0,b1

    const int z = blockIdx.z, zo = z / innerCnt, zi = z - zo * innerCnt;
    const __half* Ah = Ahi + (size_t)zo * aO + (size_t)zi * aI;
    const __half* Al = Alo + (size_t)zo * aO + (size_t)zi * aI;
    const __half* Bh = Bhi + (size_t)zo * bO + (size_t)zi * bI;
    const __half* Bl = Blo + (size_t)zo * bO + (size_t)zi * bI;
    const long coff = (size_t)zo * cO + (size_t)zi * cI;

    const uint32_t sb = smem_u32(sm);
    const int NB = K / BK;

    // prologue: block 0 -> buf 0
    load_tile_async(Ah, lda, bm, 0, sb + 0 * TILE_B, tid);
    load_tile_async(Al, lda, bm, 0, sb + 1 * TILE_B, tid);
    load_tile_async(Bh, ldb, bn, 0, sb + 2 * TILE_B, tid);
    load_tile_async(Bl, ldb, bn, 0, sb + 3 * TILE_B, tid);
    CP_COMMIT();
    CP_WAIT0();
    __syncthreads();

    float acc[4][4][4];
#pragma unroll
    for (int i = 0; i < 4; i++)
#pragma unroll
        for (int j = 0; j < 4; j++)
#pragma unroll
            for (int t = 0; t < 4; t++) acc[i][j][t] = 0.f;

    for (int blk = 0; blk < NB; blk++) {
        const int buf = blk & 1;
        if (blk + 1 < NB) {
            const uint32_t nb = sb + (buf ^ 1) * BUF_B;
            const int kk = (blk + 1) * BK;
            load_tile_async(Ah, lda, bm, kk, nb + 0 * TILE_B, tid);
            load_tile_async(Al, lda, bm, kk, nb + 1 * TILE_B, tid);
            load_tile_async(Bh, ldb, bn, kk, nb + 2 * TILE_B, tid);
            load_tile_async(Bl, ldb, bn, kk, nb + 3 * TILE_B, tid);
            CP_COMMIT();
        }

        const uint32_t sAh = sb + buf * BUF_B + 0 * TILE_B;
        const uint32_t sAl = sb + buf * BUF_B + 1 * TILE_B;
        const uint32_t sBh = sb + buf * BUF_B + 2 * TILE_B;
        const uint32_t sBl = sb + buf * BUF_B + 3 * TILE_B;

#pragma unroll
        for (int ks = 0; ks < BK / 16; ks++) {
            const int koff = ks * 16;

            // ---- fragment loads via ldmatrix ----
            uint32_t aH[4][4], aL[4][4];
#pragma unroll
            for (int mt = 0; mt < 4; mt++) {
                const uint32_t ao = (uint32_t)(((wm + mt * 16) * ROWH + koff + aoff) * 2);
                ldsm4(aH[mt][0], aH[mt][1], aH[mt][2], aH[mt][3], sAh + ao);
                ldsm4(aL[mt][0], aL[mt][1], aL[mt][2], aL[mt][3], sAl + ao);
            }
            uint32_t bH[4][2], bL[4][2];
#pragma unroll
            for (int p = 0; p < 2; p++) {      // nt pairs (0,1) and (2,3)
                const uint32_t bo = (uint32_t)(((wn + p * 16) * ROWH + koff + boff) * 2);
                ldsm4(bH[2*p][0], bH[2*p][1], bH[2*p+1][0], bH[2*p+1][1], sBh + bo);
                ldsm4(bL[2*p][0], bL[2*p][1], bL[2*p+1][0], bL[2*p+1][1], sBl + bo);
            }

            // ---- 3 sweeps: hi*hi, lo*hi, hi*lo (16 independent mmas per sweep) --
#pragma unroll
            for (int mt = 0; mt < 4; mt++)
#pragma unroll
                for (int nt = 0; nt < 4; nt++)
                    mma16(acc[mt][nt], aH[mt], bH[nt][0], bH[nt][1]);
#pragma unroll
            for (int mt = 0; mt < 4; mt++)
#pragma unroll
                for (int nt = 0; nt < 4; nt++)
                    mma16(acc[mt][nt], aL[mt], bH[nt][0], bH[nt][1]);
#pragma unroll
            for (int mt = 0; mt < 4; mt++)
#pragma unroll
                for (int nt = 0; nt < 4; nt++)
                    mma16(acc[mt][nt], aH[mt], bL[nt][0], bL[nt][1]);
        }

        if (blk + 1 < NB) CP_WAIT0();
        __syncthreads();
    }

    // ---- epilogue ----
#pragma unroll
    for (int mt = 0; mt < 4; mt++) {
#pragma unroll
        for (int half = 0; half < 2; half++) {
            const int rr = bm + wm + mt * 16 + lr + half * 8;
            float* crow = C + coff + (size_t)rr * ldc;
            const float* rrow = Rs + coff + (size_t)rr * ldc;
            __half* hrow = Chi + coff + (size_t)rr * ldc;
            __half* lrow = Clo + coff + (size_t)rr * ldc;
#pragma unroll
            for (int nt = 0; nt < 4; nt++) {
                const int col = bn + wn + nt * 8 + lc2;
                float o0 = alpha * acc[mt][nt][half * 2 + 0];
                float o1 = alpha * acc[mt][nt][half * 2 + 1];
                if (mode & EP_BIAS) {
                    const float2 bb = *(const float2*)(bias + col);
                    o0 += bb.x; o1 += bb.y;
                }
                if (mode & EP_GELU) {
                    o0 *= normcdff(o0);
                    o1 *= normcdff(o1);
                }
                if (mode & EP_RES) {
                    const float2 rv = *(const float2*)(rrow + col);
                    o0 += rv.x; o1 += rv.y;
                }
                if (mode & EP_STOREC)
                    *(float2*)(crow + col) = make_float2(o0, o1);
                if (mode & EP_SPLIT) {
                    __half h0, l0, h1, l1;
                    split16(o0, h0, l0);
                    split16(o1, h1, l1);
                    *(__half2*)(hrow + col) = __halves2half2(h0, h1);
                    *(__half2*)(lrow + col) = __halves2half2(l0, l1);
                }
            }
        }
    }
}

// ---------------- host-side launch helper -------------------------------------
static void gemm5(const __half* Ahi, const __half* Alo,
                  const __half* Bhi, const __half* Blo,
                  const float* bias, const float* res,
                  float* C, __half* Chi, __half* Clo,
                  int M, int N, int K, int lda, int ldb, int ldc, int mode,
                  float alpha = 1.f, int causal = 0, int batch = 1, int innerCnt = 1,
                  long aO = 0, long aI = 0, long bO = 0, long bI = 0,
                  long cO = 0, long cI = 0)
{
    static int attrDone = 0;
    if (!attrDone) {
        cudaFuncSetAttribute(gemm_hmma, cudaFuncAttributeMaxDynamicSharedMemorySize, SMEM_B);
        attrDone = 1;
    }
    dim3 grid(N / 128, M / 128, batch);
    gemm_hmma<<<grid, 256, SMEM_B>>>(Ahi, Alo, Bhi, Blo, bias, res, C, Chi, Clo,
                                     K, lda, ldb, ldc, innerCnt,
                                     aO, aI, bO, bI, cO, cI, alpha, mode, causal);
}

extern "C" void kernel_launch(void* const* d_in, const int* in_sizes, int n_in,
                              void* d_out, int out_size)
{
    const float* x    = (const float*)d_in[0];
    const float* ln1g = (const float*)d_in[1];
    const float* ln1b = (const float*)d_in[2];
    const float* wq   = (const float*)d_in[3];
    const float* bq   = (const float*)d_in[4];
    const float* wk   = (const float*)d_in[5];
    const float* bk   = (const float*)d_in[6];
    const float* wv   = (const float*)d_in[7];
    const float* bv   = (const float*)d_in[8];
    const float* wo   = (const float*)d_in[9];
    const float* bo   = (const float*)d_in[10];
    const float* ln2g = (const float*)d_in[11];
    const float* ln2b = (const float*)d_in[12];
    const float* w1   = (const float*)d_in[13];
    const float* b1   = (const float*)d_in[14];
    const float* w2   = (const float*)d_in[15];
    const float* b2   = (const float*)d_in[16];
    float* out = (float*)d_out;

    void* p;
#define GET(var, symn, T) cudaGetSymbolAddress(&p, symn); T* var = (T*)p
    GET(hhi, g_hhi, __half);  GET(hlo, g_hlo, __half);
    GET(qhi, g_qhi, __half);  GET(qlo, g_qlo, __half);
    GET(khi, g_khi, __half);  GET(klo, g_klo, __half);
    GET(v,   g_v,   float);
    GET(vthi,g_vthi,__half);  GET(vtlo,g_vtlo,__half);
    GET(s,   g_s,   float);
    GET(shi, g_shi, __half);  GET(slo, g_slo, __half);
    GET(aohi,g_aohi,__half);  GET(aolo,g_aolo,__half);
    GET(x1,  g_x1,  float);
    GET(h2hi,g_h2hi,__half);  GET(h2lo,g_h2lo,__half);
    GET(m1hi,g_m1hi,__half);  GET(m1lo,g_m1lo,__half);
    GET(wqthi,g_wqthi,__half); GET(wqtlo,g_wqtlo,__half);
    GET(wkthi,g_wkthi,__half); GET(wktlo,g_wktlo,__half);
    GET(wvthi,g_wvthi,__half); GET(wvtlo,g_wvtlo,__half);
    GET(wothi,g_wothi,__half); GET(wotlo,g_wotlo,__half);
    GET(w1thi,g_w1thi,__half); GET(w1tlo,g_w1tlo,__half);
    GET(w2thi,g_w2thi,__half); GET(w2tlo,g_w2tlo,__half);
#undef GET

    // weight transposes + splits: w[k][n] -> wt[n][k] fp16 hi/lo
    {
        dim3 blk(256);
        transpose_split<<<dim3(D_EMBED/32, D_EMBED/32, 1), blk>>>(wq, wqthi, wqtlo, D_EMBED, D_EMBED, 1, 0, 0, 0);
        transpose_split<<<dim3(D_EMBED/32, D_EMBED/32, 1), blk>>>(wk, wkthi, wktlo, D_EMBED, D_EMBED, 1, 0, 0, 0);
        transpose_split<<<dim3(D_EMBED/32, D_EMBED/32, 1), blk>>>(wv, wvthi, wvtlo, D_EMBED, D_EMBED, 1, 0, 0, 0);
        transpose_split<<<dim3(D_EMBED/32, D_EMBED/32, 1), blk>>>(wo, wothi, wotlo, D_EMBED, D_EMBED, 1, 0, 0, 0);
        transpose_split<<<dim3(DFF/32,     D_EMBED/32, 1), blk>>>(w1, w1thi, w1tlo, D_EMBED, DFF,     1, 0, 0, 0);
        transpose_split<<<dim3(D_EMBED/32, DFF/32,     1), blk>>>(w2, w2thi, w2tlo, DFF,     D_EMBED, 1, 0, 0, 0);
    }

    // 1. h = LN1(x) -> split
    ln_kernel<<<ROWS, 256>>>(x, ln1g, ln1b, hhi, hlo);

    // 2. Q, K (split out), V (fp32 out)
    gemm5(hhi, hlo, wqthi, wqtlo, bq, nullptr, nullptr, qhi, qlo,
          ROWS, D_EMBED, D_EMBED, D_EMBED, D_EMBED, D_EMBED, EP_BIAS | EP_SPLIT);
    gemm5(hhi, hlo, wkthi, wktlo, bk, nullptr, nullptr, khi, klo,
          ROWS, D_EMBED, D_EMBED, D_EMBED, D_EMBED, D_EMBED, EP_BIAS | EP_SPLIT);
    gemm5(hhi, hlo, wvthi, wvtlo, bv, nullptr, v, nullptr, nullptr,
          ROWS, D_EMBED, D_EMBED, D_EMBED, D_EMBED, D_EMBED, EP_BIAS | EP_STOREC);

    // 3. per-head transpose-split of V: vt[z][d][t]
    transpose_split<<<dim3(HDIM/32, SEQ/32, BH), 256>>>(
        v, vthi, vtlo, SEQ, D_EMBED, NHEAD,
        (long)SEQ * D_EMBED, (long)HDIM, (long)SEQ * HDIM);

    // 4. scores = (1/16) Q K^T  (batched over b,h; causal tile skip)
    gemm5(qhi, qlo, khi, klo, nullptr, nullptr, s, nullptr, nullptr,
          SEQ, SEQ, HDIM, D_EMBED, D_EMBED, SEQ, EP_STOREC,
          0.0625f, /*causal=*/1, BH, NHEAD,
          (long)SEQ * D_EMBED, (long)HDIM,
          (long)SEQ * D_EMBED, (long)HDIM,
          (long)NHEAD * SEQ * SEQ, (long)SEQ * SEQ);

    // 5. causal softmax -> split
    softmax_kernel<<<BH * SEQ, 256>>>(s, shi, slo);

    // 6. ao = att @ V  (split out)
    gemm5(shi, slo, vthi, vtlo, nullptr, nullptr, nullptr, aohi, aolo,
          SEQ, HDIM, SEQ, SEQ, SEQ, D_EMBED, EP_SPLIT,
          1.0f, 0, BH, NHEAD,
          (long)NHEAD * SEQ * SEQ, (long)SEQ * SEQ,
          (long)NHEAD * SEQ * HDIM, (long)SEQ * HDIM,
          (long)SEQ * D_EMBED, (long)HDIM);

    // 7. x1 = x + ao @ Wo + bo
    gemm5(aohi, aolo, wothi, wotlo, bo, x, x1, nullptr, nullptr,
          ROWS, D_EMBED, D_EMBED, D_EMBED, D_EMBED, D_EMBED,
          EP_BIAS | EP_RES | EP_STOREC);

    // 8. h2 = LN2(x1) -> split
    ln_kernel<<<ROWS, 256>>>(x1, ln2g, ln2b, h2hi, h2lo);

    // 9. m1 = gelu(h2 @ W1 + b1) -> split
    gemm5(h2hi, h2lo, w1thi, w1tlo, b1, nullptr, nullptr, m1hi, m1lo,
          ROWS, DFF, D_EMBED, D_EMBED, D_EMBED, DFF, EP_BIAS | EP_GELU | EP_SPLIT);

    // 10. out = x1 + m1 @ W2 + b2
    gemm5(m1hi, m1lo, w2thi, w2tlo, b2, x1, out, nullptr, nullptr,
          ROWS, D_EMBED, DFF, DFF, DFF, D_EMBED, EP_BIAS | EP_RES | EP_STOREC);
}

// round 7
// speedup vs baseline: 3.3539x; 2.7426x over previous
#include <cuda_runtime.h>
#include <cuda_fp16.h>
#include <math.h>
#include <stdint.h>

#define D_EMBED 2048
#define NHEAD   8
#define HDIM    256
#define BATCH   32
#define SEQ     256
#define ROWS    (BATCH*SEQ)   /* 8192 */
#define DFF     (4*D_EMBED)   /* 8192 */
#define BH      (BATCH*NHEAD) /* 256 */

// ---------------- scratch (device globals; no runtime allocation) -------------
__device__ __half g_h  [ROWS*D_EMBED];
__device__ __half g_q  [ROWS*D_EMBED];
__device__ __half g_k  [ROWS*D_EMBED];
__device__ float  g_v  [ROWS*D_EMBED];
__device__ __half g_vt [ROWS*D_EMBED];
__device__ float  g_s  [BH*SEQ*SEQ];
__device__ __half g_sh [BH*SEQ*SEQ];
__device__ __half g_ao [ROWS*D_EMBED];
__device__ float  g_x1 [ROWS*D_EMBED];
__device__ __half g_h2 [ROWS*D_EMBED];
__device__ __half g_m1 [(size_t)ROWS*DFF];
__device__ __half g_wqt[D_EMBED*D_EMBED];
__device__ __half g_wkt[D_EMBED*D_EMBED];
__device__ __half g_wvt[D_EMBED*D_EMBED];
__device__ __half g_wot[D_EMBED*D_EMBED];
__device__ __half g_w1t[(size_t)D_EMBED*DFF];
__device__ __half g_w2t[(size_t)D_EMBED*DFF];

// ---------------- helpers ------------------------------------------------------
__device__ __forceinline__ uint32_t smem_u32(const void* p) {
    uint32_t a;
    asm("{ .reg .u64 t; cvta.to.shared.u64 t, %1; cvt.u32.u64 %0, t; }" : "=r"(a) : "l"(p));
    return a;
}
__device__ __forceinline__ void cp16(uint32_t sdst, const void* gsrc) {
    asm volatile("cp.async.cg.shared.global [%0], [%1], 16;" :: "r"(sdst), "l"(gsrc));
}
#define CP_COMMIT() asm volatile("cp.async.commit_group;" ::: "memory")
#define CP_WAIT0()  asm volatile("cp.async.wait_group 0;" ::: "memory")

__device__ __forceinline__ void mma16(float* c, const uint32_t a[4],
                                      uint32_t b0, uint32_t b1) {
    asm volatile(
        "mma.sync.aligned.m16n8k16.row.col.f32.f16.f16.f32 "
        "{%0,%1,%2,%3}, {%4,%5,%6,%7}, {%8,%9}, {%0,%1,%2,%3};"
        : "+f"(c[0]), "+f"(c[1]), "+f"(c[2]), "+f"(c[3])
        : "r"(a[0]), "r"(a[1]), "r"(a[2]), "r"(a[3]), "r"(b0), "r"(b1));
}
__device__ __forceinline__ void ldsm4(uint32_t& r0, uint32_t& r1, uint32_t& r2,
                                      uint32_t& r3, uint32_t addr) {
    asm volatile("ldmatrix.sync.aligned.m8n8.x4.shared.b16 {%0,%1,%2,%3}, [%4];"
                 : "=r"(r0), "=r"(r1), "=r"(r2), "=r"(r3) : "r"(addr));
}

// ---------------- layernorm (fp32 in -> fp16 out) ------------------------------
__global__ void __launch_bounds__(256) ln_kernel(const float* __restrict__ x,
                                                 const float* __restrict__ g,
                                                 const float* __restrict__ b,
                                                 __half* __restrict__ oh)
{
    __shared__ float red[256];
    const int row = blockIdx.x;
    const float* xr = x + (size_t)row * D_EMBED;
    const int tid = threadIdx.x;

    float v[8]; float s = 0.f;
#pragma unroll
    for (int i = 0; i < 8; i++) { v[i] = xr[tid + 256*i]; s += v[i]; }
    red[tid] = s; __syncthreads();
#pragma unroll
    for (int o = 128; o > 0; o >>= 1) { if (tid < o) red[tid] += red[tid+o]; __syncthreads(); }
    const float mean = red[0] * (1.0f / D_EMBED);
    __syncthreads();
    float qv = 0.f;
#pragma unroll
    for (int i = 0; i < 8; i++) { float d = v[i] - mean; qv += d*d; }
    red[tid] = qv; __syncthreads();
#pragma unroll
    for (int o = 128; o > 0; o >>= 1) { if (tid < o) red[tid] += red[tid+o]; __syncthreads(); }
    const float rstd = rsqrtf(red[0] * (1.0f / D_EMBED) + 1e-5f);

#pragma unroll
    for (int i = 0; i < 8; i++) {
        const int c = tid + 256*i;
        float o = (v[i] - mean) * rstd * g[c] + b[c];
        oh[(size_t)row * D_EMBED + c] = __float2half_rn(o);
    }
}

// ---------------- causal softmax (fp32 in -> fp16 out) -------------------------
__global__ void __launch_bounds__(256) softmax_kernel(const float* __restrict__ s,
                                                      __half* __restrict__ oh)
{
    __shared__ float red[256];
    const int row = blockIdx.x;
    const int t = row & (SEQ - 1);
    const float* sr = s + (size_t)row * SEQ;
    const int tid = threadIdx.x;

    const float val = (tid <= t) ? sr[tid] : -INFINITY;
    red[tid] = val; __syncthreads();
#pragma unroll
    for (int o = 128; o > 0; o >>= 1) { if (tid < o) red[tid] = fmaxf(red[tid], red[tid+o]); __syncthreads(); }
    const float mx = red[0];
    __syncthreads();
    const float e = (tid <= t) ? expf(val - mx) : 0.f;
    red[tid] = e; __syncthreads();
#pragma unroll
    for (int o = 128; o > 0; o >>= 1) { if (tid < o) red[tid] += red[tid+o]; __syncthreads(); }
    oh[(size_t)row * SEQ + tid] = __float2half_rn(e / red[0]);
}

// ---------------- transpose: fp32 [R x C] -> fp16 [C x R] ----------------------
__global__ void __launch_bounds__(256) transpose_h(
    const float* __restrict__ src, __half* __restrict__ dh,
    int R, int lds, int innerCnt, long sO, long sI, long dStride)
{
    __shared__ float t[32][33];
    const int z = blockIdx.z;
    const int zo = z / innerCnt, zi = z - zo * innerCnt;
    const float* s = src + (size_t)zo * sO + (size_t)zi * sI;
    __half* hh = dh + (size_t)z * dStride;
    const int c0 = blockIdx.x * 32, r0 = blockIdx.y * 32;
    const int x = threadIdx.x & 31, y = threadIdx.x >> 5;  // 32 x 8
#pragma unroll
    for (int i = 0; i < 32; i += 8)
        t[y + i][x] = s[(size_t)(r0 + y + i) * lds + c0 + x];
    __syncthreads();
#pragma unroll
    for (int i = 0; i < 32; i += 8)
        hh[(size_t)(c0 + y + i) * R + r0 + x] = __float2half_rn(t[x][y + i]);
}

// ---------------- plain fp16 mma.sync GEMM: 128x128 tile, BK=64 ----------------
// 8 warps: 2 (M) x 4 (N); warp tile 64x32. ldmatrix loads, 2 CTAs/SM.
#define EP_BIAS   1
#define EP_GELU   2
#define EP_RES    4
#define EP_HALF   8
#define EP_STOREC 16

#define BK      64
#define ROWH    72                      /* halves per smem row (pad 64+8)  */
#define ROWB    (ROWH*2)                /* 144 bytes                        */
#define TILE_B  (128 * ROWB)            /* 18432 bytes per tile             */
#define BUF_B   (2 * TILE_B)            /* A,B = 36864                      */
#define SMEM_B  (2 * BUF_B)             /* double buffered = 73728          */

__device__ __forceinline__ void load_tile_async(const __half* __restrict__ G, int ld,
                                                int row0, int k0, uint32_t sbase, int tid)
{
#pragma unroll
    for (int it = 0; it < 4; it++) {
        const int c = tid + it * 256;         // 0..1023
        const int r = c >> 3, cb = c & 7;
        cp16(sbase + r * ROWB + cb * 16,
             G + (size_t)(row0 + r) * ld + k0 + cb * 8);
    }
}

__global__ void __launch_bounds__(256, 2) gemm_hmma(
    const __half* __restrict__ A, const __half* __restrict__ B,
    const float* __restrict__ bias, const float* __restrict__ Rs,
    float* __restrict__ C, __half* __restrict__ Ch,
    int K, int lda, int ldb, int ldc, int innerCnt,
    long aO, long aI, long bO, long bI, long cO, long cI,
    float alpha, int mode, int causal)
{
    extern __shared__ __align__(128) char sm[];

    const int bm = blockIdx.y * 128;
    const int bn = blockIdx.x * 128;
    if (causal && bn > bm) return;

    const int tid = threadIdx.x, wid = tid >> 5, lane = tid & 31;
    const int wm = (wid >> 2) * 64;     // 0 or 64
    const int wn = (wid & 3) * 32;      // 0,32,64,96
    const int lr = lane >> 2;           // 0..7
    const int lc2 = (lane & 3) * 2;     // 0,2,4,6

    // ldmatrix per-lane offsets (halves within a tile)
    const int q = lane >> 3, rw = lane & 7;
    const int aoff = ((q & 1) * 8 + rw) * ROWH + (q >> 1) * 8;  // A: x4 -> a0..a3
    const int boff = ((q >> 1) * 8 + rw) * ROWH + (q & 1) * 8;  // B: x4 -> nt-pair

    const int z = blockIdx.z, zo = z / innerCnt, zi = z - zo * innerCnt;
    const __half* Ag = A + (size_t)zo * aO + (size_t)zi * aI;
    const __half* Bg = B + (size_t)zo * bO + (size_t)zi * bI;
    const long coff = (size_t)zo * cO + (size_t)zi * cI;

    const uint32_t sb = smem_u32(sm);
    const int NB = K / BK;

    // prologue
    load_tile_async(Ag, lda, bm, 0, sb + 0 * TILE_B, tid);
    load_tile_async(Bg, ldb, bn, 0, sb + 1 * TILE_B, tid);
    CP_COMMIT();
    CP_WAIT0();
    __syncthreads();

    float acc[4][4][4];
#pragma unroll
    for (int i = 0; i < 4; i++)
#pragma unroll
        for (int j = 0; j < 4; j++)
#pragma unroll
            for (int t = 0; t < 4; t++) acc[i][j][t] = 0.f;

    for (int blk = 0; blk < NB; blk++) {
        const int buf = blk & 1;
        if (blk + 1 < NB) {
            const uint32_t nb = sb + (buf ^ 1) * BUF_B;
            const int kk = (blk + 1) * BK;
            load_tile_async(Ag, lda, bm, kk, nb + 0 * TILE_B, tid);
            load_tile_async(Bg, ldb, bn, kk, nb + 1 * TILE_B, tid);
            CP_COMMIT();
        }

        const uint32_t sA = sb + buf * BUF_B + 0 * TILE_B;
        const uint32_t sB = sb + buf * BUF_B + 1 * TILE_B;

#pragma unroll
        for (int ks = 0; ks < BK / 16; ks++) {
            const int koff = ks * 16;

            uint32_t aF[4][4];
#pragma unroll
            for (int mt = 0; mt < 4; mt++) {
                const uint32_t ao = (uint32_t)(((wm + mt * 16) * ROWH + koff + aoff) * 2);
                ldsm4(aF[mt][0], aF[mt][1], aF[mt][2], aF[mt][3], sA + ao);
            }
            uint32_t bF[4][2];
#pragma unroll
            for (int p = 0; p < 2; p++) {
                const uint32_t bo = (uint32_t)(((wn + p * 16) * ROWH + koff + boff) * 2);
                ldsm4(bF[2*p][0], bF[2*p][1], bF[2*p+1][0], bF[2*p+1][1], sB + bo);
            }
#pragma unroll
            for (int mt = 0; mt < 4; mt++)
#pragma unroll
                for (int nt = 0; nt < 4; nt++)
                    mma16(acc[mt][nt], aF[mt], bF[nt][0], bF[nt][1]);
        }

        if (blk + 1 < NB) CP_WAIT0();
        __syncthreads();
    }

    // ---- epilogue ----
#pragma unroll
    for (int mt = 0; mt < 4; mt++) {
#pragma unroll
        for (int half = 0; half < 2; half++) {
            const int rr = bm + wm + mt * 16 + lr + half * 8;
            float* crow = C + coff + (size_t)rr * ldc;
            const float* rrow = Rs + coff + (size_t)rr * ldc;
            __half* hrow = Ch + coff + (size_t)rr * ldc;
#pragma unroll
            for (int nt = 0; nt < 4; nt++) {
                const int col = bn + wn + nt * 8 + lc2;
                float o0 = alpha * acc[mt][nt][half * 2 + 0];
                float o1 = alpha * acc[mt][nt][half * 2 + 1];
                if (mode & EP_BIAS) {
                    const float2 bb = *(const float2*)(bias + col);
                    o0 += bb.x; o1 += bb.y;
                }
                if (mode & EP_GELU) {
                    o0 *= normcdff(o0);
                    o1 *= normcdff(o1);
                }
                if (mode & EP_RES) {
                    const float2 rv = *(const float2*)(rrow + col);
                    o0 += rv.x; o1 += rv.y;
                }
                if (mode & EP_STOREC)
                    *(float2*)(crow + col) = make_float2(o0, o1);
                if (mode & EP_HALF)
                    *(__half2*)(hrow + col) =
                        __halves2half2(__float2half_rn(o0), __float2half_rn(o1));
            }
        }
    }
}

// ---------------- host-side launch helper -------------------------------------
static void gemmH(const __half* A, const __half* B,
                  const float* bias, const float* res,
                  float* C, __half* Ch,
                  int M, int N, int K, int lda, int ldb, int ldc, int mode,
                  float alpha = 1.f, int causal = 0, int batch = 1, int innerCnt = 1,
                  long aO = 0, long aI = 0, long bO = 0, long bI = 0,
                  long cO = 0, long cI = 0)
{
    static int attrDone = 0;
    if (!attrDone) {
        cudaFuncSetAttribute(gemm_hmma, cudaFuncAttributeMaxDynamicSharedMemorySize, SMEM_B);
        attrDone = 1;
    }
    dim3 grid(N / 128, M / 128, batch);
    gemm_hmma<<<grid, 256, SMEM_B>>>(A, B, bias, res, C, Ch,
                                     K, lda, ldb, ldc, innerCnt,
                                     aO, aI, bO, bI, cO, cI, alpha, mode, causal);
}

extern "C" void kernel_launch(void* const* d_in, const int* in_sizes, int n_in,
                              void* d_out, int out_size)
{
    const float* x    = (const float*)d_in[0];
    const float* ln1g = (const float*)d_in[1];
    const float* ln1b = (const float*)d_in[2];
    const float* wq   = (const float*)d_in[3];
    const float* bq   = (const float*)d_in[4];
    const float* wk   = (const float*)d_in[5];
    const float* bk   = (const float*)d_in[6];
    const float* wv   = (const float*)d_in[7];
    const float* bv   = (const float*)d_in[8];
    const float* wo   = (const float*)d_in[9];
    const float* bo   = (const float*)d_in[10];
    const float* ln2g = (const float*)d_in[11];
    const float* ln2b = (const float*)d_in[12];
    const float* w1   = (const float*)d_in[13];
    const float* b1   = (const float*)d_in[14];
    const float* w2   = (const float*)d_in[15];
    const float* b2   = (const float*)d_in[16];
    float* out = (float*)d_out;

    void* p;
#define GET(var, symn, T) cudaGetSymbolAddress(&p, symn); T* var = (T*)p
    GET(h,   g_h,   __half);
    GET(q,   g_q,   __half);
    GET(k,   g_k,   __half);
    GET(v,   g_v,   float);
    GET(vt,  g_vt,  __half);
    GET(s,   g_s,   float);
    GET(sh,  g_sh,  __half);
    GET(ao,  g_ao,  __half);
    GET(x1,  g_x1,  float);
    GET(h2,  g_h2,  __half);
    GET(m1,  g_m1,  __half);
    GET(wqt, g_wqt, __half);
    GET(wkt, g_wkt, __half);
    GET(wvt, g_wvt, __half);
    GET(wot, g_wot, __half);
    GET(w1t, g_w1t, __half);
    GET(w2t, g_w2t, __half);
#undef GET

    // weight transposes: w[k][n] -> wt[n][k] fp16
    {
        dim3 blk(256);
        transpose_h<<<dim3(D_EMBED/32, D_EMBED/32, 1), blk>>>(wq, wqt, D_EMBED, D_EMBED, 1, 0, 0, 0);
        transpose_h<<<dim3(D_EMBED/32, D_EMBED/32, 1), blk>>>(wk, wkt, D_EMBED, D_EMBED, 1, 0, 0, 0);
        transpose_h<<<dim3(D_EMBED/32, D_EMBED/32, 1), blk>>>(wv, wvt, D_EMBED, D_EMBED, 1, 0, 0, 0);
        transpose_h<<<dim3(D_EMBED/32, D_EMBED/32, 1), blk>>>(wo, wot, D_EMBED, D_EMBED, 1, 0, 0, 0);
        transpose_h<<<dim3(DFF/32,     D_EMBED/32, 1), blk>>>(w1, w1t, D_EMBED, DFF,     1, 0, 0, 0);
        transpose_h<<<dim3(D_EMBED/32, DFF/32,     1), blk>>>(w2, w2t, DFF,     D_EMBED, 1, 0, 0, 0);
    }

    // 1. h = LN1(x)
    ln_kernel<<<ROWS, 256>>>(x, ln1g, ln1b, h);

    // 2. Q, K (fp16 out), V (fp32 out)
    gemmH(h, wqt, bq, nullptr, nullptr, q,
          ROWS, D_EMBED, D_EMBED, D_EMBED, D_EMBED, D_EMBED, EP_BIAS | EP_HALF);
    gemmH(h, wkt, bk, nullptr, nullptr, k,
          ROWS, D_EMBED, D_EMBED, D_EMBED, D_EMBED, D_EMBED, EP_BIAS | EP_HALF);
    gemmH(h, wvt, bv, nullptr, v, nullptr,
          ROWS, D_EMBED, D_EMBED, D_EMBED, D_EMBED, D_EMBED, EP_BIAS | EP_STOREC);

    // 3. per-head transpose of V: vt[z][d][t]
    transpose_h<<<dim3(HDIM/32, SEQ/32, BH), 256>>>(
        v, vt, SEQ, D_EMBED, NHEAD,
        (long)SEQ * D_EMBED, (long)HDIM, (long)SEQ * HDIM);

    // 4. scores = (1/16) Q K^T  (batched over b,h; causal tile skip)
    gemmH(q, k, nullptr, nullptr, s, nullptr,
          SEQ, SEQ, HDIM, D_EMBED, D_EMBED, SEQ, EP_STOREC,
          0.0625f, /*causal=*/1, BH, NHEAD,
          (long)SEQ * D_EMBED, (long)HDIM,
          (long)SEQ * D_EMBED, (long)HDIM,
          (long)NHEAD * SEQ * SEQ, (long)SEQ * SEQ);

    // 5. causal softmax -> fp16
    softmax_kernel<<<BH * SEQ, 256>>>(s, sh);

    // 6. ao = att @ V  (fp16 out)
    gemmH(sh, vt, nullptr, nullptr, nullptr, ao,
          SEQ, HDIM, SEQ, SEQ, SEQ, D_EMBED, EP_HALF,
          1.0f, 0, BH, NHEAD,
          (long)NHEAD * SEQ * SEQ, (long)SEQ * SEQ,
          (long)NHEAD * SEQ * HDIM, (long)SEQ * HDIM,
          (long)SEQ * D_EMBED, (long)HDIM);

    // 7. x1 = x + ao @ Wo + bo
    gemmH(ao, wot, bo, x, x1, nullptr,
          ROWS, D_EMBED, D_EMBED, D_EMBED, D_EMBED, D_EMBED,
          EP_BIAS | EP_RES | EP_STOREC);

    // 8. h2 = LN2(x1)
    ln_kernel<<<ROWS, 256>>>(x1, ln2g, ln2b, h2);

    // 9. m1 = gelu(h2 @ W1 + b1) -> fp16
    gemmH(h2, w1t, b1, nullptr, nullptr, m1,
          ROWS, DFF, D_EMBED, D_EMBED, D_EMBED, DFF, EP_BIAS | EP_GELU | EP_HALF);

    // 10. out = x1 + m1 @ W2 + b2
    gemmH(m1, w2t, b2, x1, out, nullptr,
          ROWS, D_EMBED, DFF, DFF, DFF, D_EMBED, EP_BIAS | EP_RES | EP_STOREC);
}

// round 8
// speedup vs baseline: 3.7092x; 1.1059x over previous
#include <cuda_runtime.h>
#include <cuda_fp16.h>
#include <math.h>
#include <stdint.h>

#define D_EMBED 2048
#define NHEAD   8
#define HDIM    256
#define BATCH   32
#define SEQ     256
#define ROWS    (BATCH*SEQ)   /* 8192 */
#define DFF     (4*D_EMBED)   /* 8192 */
#define BH      (BATCH*NHEAD) /* 256 */
#define NQKV    (3*D_EMBED)   /* 6144 */

// ---------------- scratch (device globals; no runtime allocation) -------------
__device__ __half g_h  [ROWS*D_EMBED];
__device__ __half g_qkv[(size_t)ROWS*NQKV];
__device__ __half g_vt [ROWS*D_EMBED];
__device__ float  g_s  [BH*SEQ*SEQ];
__device__ __half g_sh [BH*SEQ*SEQ];
__device__ __half g_ao [ROWS*D_EMBED];
__device__ float  g_x1 [ROWS*D_EMBED];
__device__ __half g_h2 [ROWS*D_EMBED];
__device__ __half g_m1 [(size_t)ROWS*DFF];
__device__ __half g_wqkvt[(size_t)NQKV*D_EMBED];
__device__ __half g_wot[D_EMBED*D_EMBED];
__device__ __half g_w1t[(size_t)D_EMBED*DFF];
__device__ __half g_w2t[(size_t)D_EMBED*DFF];
__device__ float  g_bqkv[NQKV];

// ---------------- helpers ------------------------------------------------------
__device__ __forceinline__ uint32_t smem_u32(const void* p) {
    uint32_t a;
    asm("{ .reg .u64 t; cvta.to.shared.u64 t, %1; cvt.u32.u64 %0, t; }" : "=r"(a) : "l"(p));
    return a;
}
__device__ __forceinline__ void cp16(uint32_t sdst, const void* gsrc) {
    asm volatile("cp.async.cg.shared.global [%0], [%1], 16;" :: "r"(sdst), "l"(gsrc));
}
#define CP_COMMIT() asm volatile("cp.async.commit_group;" ::: "memory")
template<int N>
__device__ __forceinline__ void cp_wait() {
    asm volatile("cp.async.wait_group %0;" :: "n"(N) : "memory");
}

__device__ __forceinline__ void mma16(float* c, const uint32_t a[4],
                                      uint32_t b0, uint32_t b1) {
    asm volatile(
        "mma.sync.aligned.m16n8k16.row.col.f32.f16.f16.f32 "
        "{%0,%1,%2,%3}, {%4,%5,%6,%7}, {%8,%9}, {%0,%1,%2,%3};"
        : "+f"(c[0]), "+f"(c[1]), "+f"(c[2]), "+f"(c[3])
        : "r"(a[0]), "r"(a[1]), "r"(a[2]), "r"(a[3]), "r"(b0), "r"(b1));
}
__device__ __forceinline__ void ldsm4(uint32_t& r0, uint32_t& r1, uint32_t& r2,
                                      uint32_t& r3, uint32_t addr) {
    asm volatile("ldmatrix.sync.aligned.m8n8.x4.shared.b16 {%0,%1,%2,%3}, [%4];"
                 : "=r"(r0), "=r"(r1), "=r"(r2), "=r"(r3) : "r"(addr));
}

// ---------------- layernorm (fp32 in -> fp16 out) ------------------------------
__global__ void __launch_bounds__(256) ln_kernel(const float* __restrict__ x,
                                                 const float* __restrict__ g,
                                                 const float* __restrict__ b,
                                                 __half* __restrict__ oh)
{
    __shared__ float red[256];
    const int row = blockIdx.x;
    const float* xr = x + (size_t)row * D_EMBED;
    const int tid = threadIdx.x;

    float v[8]; float s = 0.f;
#pragma unroll
    for (int i = 0; i < 8; i++) { v[i] = xr[tid + 256*i]; s += v[i]; }
    red[tid] = s; __syncthreads();
#pragma unroll
    for (int o = 128; o > 0; o >>= 1) { if (tid < o) red[tid] += red[tid+o]; __syncthreads(); }
    const float mean = red[0] * (1.0f / D_EMBED);
    __syncthreads();
    float qv = 0.f;
#pragma unroll
    for (int i = 0; i < 8; i++) { float d = v[i] - mean; qv += d*d; }
    red[tid] = qv; __syncthreads();
#pragma unroll
    for (int o = 128; o > 0; o >>= 1) { if (tid < o) red[tid] += red[tid+o]; __syncthreads(); }
    const float rstd = rsqrtf(red[0] * (1.0f / D_EMBED) + 1e-5f);

#pragma unroll
    for (int i = 0; i < 8; i++) {
        const int c = tid + 256*i;
        float o = (v[i] - mean) * rstd * g[c] + b[c];
        oh[(size_t)row * D_EMBED + c] = __float2half_rn(o);
    }
}

// ---------------- causal softmax (fp32 in -> fp16 out) -------------------------
__global__ void __launch_bounds__(256) softmax_kernel(const float* __restrict__ s,
                                                      __half* __restrict__ oh)
{
    __shared__ float red[256];
    const int row = blockIdx.x;
    const int t = row & (SEQ - 1);
    const float* sr = s + (size_t)row * SEQ;
    const int tid = threadIdx.x;

    const float val = (tid <= t) ? sr[tid] : -INFINITY;
    red[tid] = val; __syncthreads();
#pragma unroll
    for (int o = 128; o > 0; o >>= 1) { if (tid < o) red[tid] = fmaxf(red[tid], red[tid+o]); __syncthreads(); }
    const float mx = red[0];
    __syncthreads();
    const float e = (tid <= t) ? expf(val - mx) : 0.f;
    red[tid] = e; __syncthreads();
#pragma unroll
    for (int o = 128; o > 0; o >>= 1) { if (tid < o) red[tid] += red[tid+o]; __syncthreads(); }
    oh[(size_t)row * SEQ + tid] = __float2half_rn(e / red[0]);
}

// ---------------- transpose: fp32 [R' x C] -> fp16 [C x R] ---------------------
__global__ void __launch_bounds__(256) transpose_h(
    const float* __restrict__ src, __half* __restrict__ dh,
    int R, int lds, int innerCnt, long sO, long sI, long dStride)
{
    __shared__ float t[32][33];
    const int z = blockIdx.z;
    const int zo = z / innerCnt, zi = z - zo * innerCnt;
    const float* s = src + (size_t)zo * sO + (size_t)zi * sI;
    __half* hh = dh + (size_t)z * dStride;
    const int c0 = blockIdx.x * 32, r0 = blockIdx.y * 32;
    const int x = threadIdx.x & 31, y = threadIdx.x >> 5;  // 32 x 8
#pragma unroll
    for (int i = 0; i < 32; i += 8)
        t[y + i][x] = s[(size_t)(r0 + y + i) * lds + c0 + x];
    __syncthreads();
#pragma unroll
    for (int i = 0; i < 32; i += 8)
        hh[(size_t)(c0 + y + i) * R + r0 + x] = __float2half_rn(t[x][y + i]);
}

// ---------------- transpose: fp16 [R' x C] -> fp16 [C x R] ---------------------
__global__ void __launch_bounds__(256) transpose_hh(
    const __half* __restrict__ src, __half* __restrict__ dh,
    int R, int lds, int innerCnt, long sO, long sI, long dStride)
{
    __shared__ __half t[32][34];
    const int z = blockIdx.z;
    const int zo = z / innerCnt, zi = z - zo * innerCnt;
    const __half* s = src + (size_t)zo * sO + (size_t)zi * sI;
    __half* hh = dh + (size_t)z * dStride;
    const int c0 = blockIdx.x * 32, r0 = blockIdx.y * 32;
    const int x = threadIdx.x & 31, y = threadIdx.x >> 5;
#pragma unroll
    for (int i = 0; i < 32; i += 8)
        t[y + i][x] = s[(size_t)(r0 + y + i) * lds + c0 + x];
    __syncthreads();
#pragma unroll
    for (int i = 0; i < 32; i += 8)
        hh[(size_t)(c0 + y + i) * R + r0 + x] = t[x][y + i];
}

// ---------------- pack 3 biases into one buffer --------------------------------
__global__ void __launch_bounds__(256) pack3(const float* __restrict__ a,
                                             const float* __restrict__ b,
                                             const float* __restrict__ c,
                                             float* __restrict__ o)
{
    const int i = blockIdx.x * 256 + threadIdx.x;
    o[i] = (i < 2048) ? a[i] : ((i < 4096) ? b[i - 2048] : c[i - 4096]);
}

// ---------------- fp16 mma.sync GEMM: 128x128 tile, 4 warps (64x64), BK=64 -----
// 3-stage cp.async pipeline, 2 CTAs/SM.
#define EP_BIAS   1
#define EP_GELU   2
#define EP_RES    4
#define EP_HALF   8
#define EP_STOREC 16

#define BK      64
#define ROWH    72                      /* halves per smem row (pad 64+8)  */
#define ROWB    (ROWH*2)                /* 144 bytes                        */
#define TILE_B  (128 * ROWB)            /* 18432 bytes per tile             */
#define BUF_B   (2 * TILE_B)            /* A,B = 36864                      */
#define SMEM_B  (3 * BUF_B)             /* 3 stages = 110592                */

// load 1/4 of an (A,B) tile pair; part in [0,4)
__device__ __forceinline__ void load_part(const __half* __restrict__ Ag, int lda,
                                          const __half* __restrict__ Bg, int ldb,
                                          int bm, int bn, int k0,
                                          uint32_t sbase, int tid, int part)
{
#pragma unroll
    for (int i = 0; i < 2; i++) {
        const int c = (part * 2 + i) * 128 + tid;   // 0..1023
        const int r = c >> 3, cb = c & 7;
        cp16(sbase + r * ROWB + cb * 16,
             Ag + (size_t)(bm + r) * lda + k0 + cb * 8);
        cp16(sbase + TILE_B + r * ROWB + cb * 16,
             Bg + (size_t)(bn + r) * ldb + k0 + cb * 8);
    }
}

__global__ void __launch_bounds__(128, 2) gemm_hmma(
    const __half* __restrict__ A, const __half* __restrict__ B,
    const float* __restrict__ bias, const float* __restrict__ Rs,
    float* __restrict__ C, __half* __restrict__ Ch,
    int K, int lda, int ldb, int ldc, int innerCnt,
    long aO, long aI, long bO, long bI, long cO, long cI,
    float alpha, int mode, int causal)
{
    extern __shared__ __align__(128) char sm[];

    const int bm = blockIdx.y * 128;
    const int bn = blockIdx.x * 128;
    if (causal && bn > bm) return;

    const int tid = threadIdx.x, wid = tid >> 5, lane = tid & 31;
    const int wm = (wid >> 1) * 64;     // 0 or 64
    const int wn = (wid & 1) * 64;      // 0 or 64
    const int lr = lane >> 2;           // 0..7
    const int lc2 = (lane & 3) * 2;     // 0,2,4,6

    // ldmatrix per-lane offsets (halves within a tile)
    const int q = lane >> 3, rw = lane & 7;
    const int aoff = ((q & 1) * 8 + rw) * ROWH + (q >> 1) * 8;
    const int boff = ((q >> 1) * 8 + rw) * ROWH + (q & 1) * 8;

    const int z = blockIdx.z, zo = z / innerCnt, zi = z - zo * innerCnt;
    const __half* Ag = A + (size_t)zo * aO + (size_t)zi * aI;
    const __half* Bg = B + (size_t)zo * bO + (size_t)zi * bI;
    const long coff = (size_t)zo * cO + (size_t)zi * cI;

    const uint32_t sb = smem_u32(sm);
    const int NB = K / BK;

    // prologue: stages 0 and 1
#pragma unroll
    for (int part = 0; part < 4; part++)
        load_part(Ag, lda, Bg, ldb, bm, bn, 0, sb, tid, part);
    CP_COMMIT();
#pragma unroll
    for (int part = 0; part < 4; part++)
        load_part(Ag, lda, Bg, ldb, bm, bn, BK, sb + BUF_B, tid, part);
    CP_COMMIT();

    float acc[4][8][4];
#pragma unroll
    for (int i = 0; i < 4; i++)
#pragma unroll
        for (int j = 0; j < 8; j++)
#pragma unroll
            for (int t = 0; t < 4; t++) acc[i][j][t] = 0.f;

    for (int blk = 0; blk < NB; blk++) {
        if (blk + 1 < NB) cp_wait<1>(); else cp_wait<0>();
        __syncthreads();

        const int stage = blk % 3;
        const uint32_t sA = sb + stage * BUF_B;
        const uint32_t sB = sA + TILE_B;
        const bool next2 = (blk + 2 < NB);
        const int nstage = (blk + 2) % 3;
        const int nk = (blk + 2) * BK;

#pragma unroll
        for (int ks = 0; ks < BK / 16; ks++) {
            const int koff = ks * 16;

            uint32_t aF[4][4];
#pragma unroll
            for (int mt = 0; mt < 4; mt++) {
                const uint32_t ao = (uint32_t)(((wm + mt * 16) * ROWH + koff + aoff) * 2);
                ldsm4(aF[mt][0], aF[mt][1], aF[mt][2], aF[mt][3], sA + ao);
            }
            uint32_t bF[8][2];
#pragma unroll
            for (int p = 0; p < 4; p++) {
                const uint32_t bo = (uint32_t)(((wn + p * 16) * ROWH + koff + boff) * 2);
                ldsm4(bF[2*p][0], bF[2*p][1], bF[2*p+1][0], bF[2*p+1][1], sB + bo);
            }

            if (next2)
                load_part(Ag, lda, Bg, ldb, bm, bn, nk, sb + nstage * BUF_B, tid, ks);

#pragma unroll
            for (int mt = 0; mt < 4; mt++)
#pragma unroll
                for (int nt = 0; nt < 8; nt++)
                    mma16(acc[mt][nt], aF[mt], bF[nt][0], bF[nt][1]);
        }
        if (next2) CP_COMMIT();
    }

    // ---- epilogue ----
#pragma unroll
    for (int mt = 0; mt < 4; mt++) {
#pragma unroll
        for (int half = 0; half < 2; half++) {
            const int rr = bm + wm + mt * 16 + lr + half * 8;
            float* crow = C + coff + (size_t)rr * ldc;
            const float* rrow = Rs + coff + (size_t)rr * ldc;
            __half* hrow = Ch + coff + (size_t)rr * ldc;
#pragma unroll
            for (int nt = 0; nt < 8; nt++) {
                const int col = bn + wn + nt * 8 + lc2;
                float o0 = alpha * acc[mt][nt][half * 2 + 0];
                float o1 = alpha * acc[mt][nt][half * 2 + 1];
                if (mode & EP_BIAS) {
                    const float2 bb = *(const float2*)(bias + col);
                    o0 += bb.x; o1 += bb.y;
                }
                if (mode & EP_GELU) {
                    o0 *= normcdff(o0);
                    o1 *= normcdff(o1);
                }
                if (mode & EP_RES) {
                    const float2 rv = *(const float2*)(rrow + col);
                    o0 += rv.x; o1 += rv.y;
                }
                if (mode & EP_STOREC)
                    *(float2*)(crow + col) = make_float2(o0, o1);
                if (mode & EP_HALF)
                    *(__half2*)(hrow + col) =
                        __halves2half2(__float2half_rn(o0), __float2half_rn(o1));
            }
        }
    }
}

// ---------------- host-side launch helper -------------------------------------
static void gemmH(const __half* A, const __half* B,
                  const float* bias, const float* res,
                  float* C, __half* Ch,
                  int M, int N, int K, int lda, int ldb, int ldc, int mode,
                  float alpha = 1.f, int causal = 0, int batch = 1, int innerCnt = 1,
                  long aO = 0, long aI = 0, long bO = 0, long bI = 0,
                  long cO = 0, long cI = 0)
{
    static int attrDone = 0;
    if (!attrDone) {
        cudaFuncSetAttribute(gemm_hmma, cudaFuncAttributeMaxDynamicSharedMemorySize, SMEM_B);
        attrDone = 1;
    }
    dim3 grid(N / 128, M / 128, batch);
    gemm_hmma<<<grid, 128, SMEM_B>>>(A, B, bias, res, C, Ch,
                                     K, lda, ldb, ldc, innerCnt,
                                     aO, aI, bO, bI, cO, cI, alpha, mode, causal);
}

extern "C" void kernel_launch(void* const* d_in, const int* in_sizes, int n_in,
                              void* d_out, int out_size)
{
    const float* x    = (const float*)d_in[0];
    const float* ln1g = (const float*)d_in[1];
    const float* ln1b = (const float*)d_in[2];
    const float* wq   = (const float*)d_in[3];
    const float* bq   = (const float*)d_in[4];
    const float* wk   = (const float*)d_in[5];
    const float* bk   = (const float*)d_in[6];
    const float* wv   = (const float*)d_in[7];
    const float* bv   = (const float*)d_in[8];
    const float* wo   = (const float*)d_in[9];
    const float* bo   = (const float*)d_in[10];
    const float* ln2g = (const float*)d_in[11];
    const float* ln2b = (const float*)d_in[12];
    const float* w1   = (const float*)d_in[13];
    const float* b1   = (const float*)d_in[14];
    const float* w2   = (const float*)d_in[15];
    const float* b2   = (const float*)d_in[16];
    float* out = (float*)d_out;

    void* p;
#define GET(var, symn, T) cudaGetSymbolAddress(&p, symn); T* var = (T*)p
    GET(h,    g_h,    __half);
    GET(qkv,  g_qkv,  __half);
    GET(vt,   g_vt,   __half);
    GET(s,    g_s,    float);
    GET(sh,   g_sh,   __half);
    GET(ao,   g_ao,   __half);
    GET(x1,   g_x1,   float);
    GET(h2,   g_h2,   __half);
    GET(m1,   g_m1,   __half);
    GET(wqkvt,g_wqkvt,__half);
    GET(wot,  g_wot,  __half);
    GET(w1t,  g_w1t,  __half);
    GET(w2t,  g_w2t,  __half);
    GET(bqkv, g_bqkv, float);
#undef GET

    // weight transposes: w[k][n] -> wt[n][k] fp16; qkv weights concatenated
    {
        dim3 blk(256);
        transpose_h<<<dim3(D_EMBED/32, D_EMBED/32, 1), blk>>>(wq, wqkvt,                   D_EMBED, D_EMBED, 1, 0, 0, 0);
        transpose_h<<<dim3(D_EMBED/32, D_EMBED/32, 1), blk>>>(wk, wqkvt + 2048*2048,       D_EMBED, D_EMBED, 1, 0, 0, 0);
        transpose_h<<<dim3(D_EMBED/32, D_EMBED/32, 1), blk>>>(wv, wqkvt + 2*2048*2048,     D_EMBED, D_EMBED, 1, 0, 0, 0);
        transpose_h<<<dim3(D_EMBED/32, D_EMBED/32, 1), blk>>>(wo, wot, D_EMBED, D_EMBED, 1, 0, 0, 0);
        transpose_h<<<dim3(DFF/32,     D_EMBED/32, 1), blk>>>(w1, w1t, D_EMBED, DFF,     1, 0, 0, 0);
        transpose_h<<<dim3(D_EMBED/32, DFF/32,     1), blk>>>(w2, w2t, DFF,     D_EMBED, 1, 0, 0, 0);
        pack3<<<NQKV/256, 256>>>(bq, bk, bv, bqkv);
    }

    // 1. h = LN1(x)
    ln_kernel<<<ROWS, 256>>>(x, ln1g, ln1b, h);

    // 2. fused QKV projection: qkv[t][0:6144] (all fp16)
    gemmH(h, wqkvt, bqkv, nullptr, nullptr, qkv,
          ROWS, NQKV, D_EMBED, D_EMBED, D_EMBED, NQKV, EP_BIAS | EP_HALF);

    // 3. per-head transpose of V (fp16): vt[z][d][t]
    transpose_hh<<<dim3(HDIM/32, SEQ/32, BH), 256>>>(
        qkv + 4096, vt, SEQ, NQKV, NHEAD,
        (long)SEQ * NQKV, (long)HDIM, (long)SEQ * HDIM);

    // 4. scores = (1/16) Q K^T  (batched over b,h; causal tile skip)
    gemmH(qkv, qkv + 2048, nullptr, nullptr, s, nullptr,
          SEQ, SEQ, HDIM, NQKV, NQKV, SEQ, EP_STOREC,
          0.0625f, /*causal=*/1, BH, NHEAD,
          (long)SEQ * NQKV, (long)HDIM,
          (long)SEQ * NQKV, (long)HDIM,
          (long)NHEAD * SEQ * SEQ, (long)SEQ * SEQ);

    // 5. causal softmax -> fp16
    softmax_kernel<<<BH * SEQ, 256>>>(s, sh);

    // 6. ao = att @ V  (fp16 out)
    gemmH(sh, vt, nullptr, nullptr, nullptr, ao,
          SEQ, HDIM, SEQ, SEQ, SEQ, D_EMBED, EP_HALF,
          1.0f, 0, BH, NHEAD,
          (long)NHEAD * SEQ * SEQ, (long)SEQ * SEQ,
          (long)NHEAD * SEQ * HDIM, (long)SEQ * HDIM,
          (long)SEQ * D_EMBED, (long)HDIM);

    // 7. x1 = x + ao @ Wo + bo
    gemmH(ao, wot, bo, x, x1, nullptr,
          ROWS, D_EMBED, D_EMBED, D_EMBED, D_EMBED, D_EMBED,
          EP_BIAS | EP_RES | EP_STOREC);

    // 8. h2 = LN2(x1)
    ln_kernel<<<ROWS, 256>>>(x1, ln2g, ln2b, h2);

    // 9. m1 = gelu(h2 @ W1 + b1) -> fp16
    gemmH(h2, w1t, b1, nullptr, nullptr, m1,
          ROWS, DFF, D_EMBED, D_EMBED, D_EMBED, DFF, EP_BIAS | EP_GELU | EP_HALF);

    // 10. out = x1 + m1 @ W2 + b2
    gemmH(m1, w2t, b2, x1, out, nullptr,
          ROWS, D_EMBED, DFF, DFF, DFF, D_EMBED, EP_BIAS | EP_RES | EP_STOREC);
}